// round 16
// baseline (speedup 1.0000x reference)
#include <cuda_runtime.h>
#include <cuda_fp16.h>
#include <mma.h>
#include <cstdint>

using namespace nvcuda;

// Problem dims (fixed)
#define BATCH 8
#define NQ    2048
#define NKV   2048
#define DQ    1024
#define DKV   1024
#define HH    256
#define NI    512            // interleaved (num,den) width
#define BPG   2              // batches per KV pipeline group
#define NGRP  (BATCH / BPG)  // 4
#define HALFB (BATCH / 2)    // 4 batches (aft part A)

// Scratch (device globals — no allocation allowed)
__device__ __half g_expwh[(size_t)BATCH * NQ * NKV]; // fp16 exp(bias)       67 MB
__device__ __half g_xqh  [BATCH * NQ * DQ];          // fp16 x_q             33.5 MB
__device__ __half g_xkvh [BATCH * NKV * DKV];        // fp16 x_kv            33.5 MB
__device__ __half g_wqh  [DQ * HH];                  // fp16 wq              0.5 MB
__device__ __half g_wkvh [DKV * NI];                 // fp16 interleaved wk|wv 1 MB
__device__ __half g_f2h  [HH * HH];                  // fp16 f2_w            0.13 MB
__device__ __half g_kvi  [BATCH * NKV * NI];         // interleaved ekv/expK 16.8 MB
__device__ __half g_sigQh[BATCH * NQ * HH];          // fp16 sigmoid(Q)      8.4 MB
__device__ __half g_Yth  [BATCH * NQ * HH];          // fp16 sig(Q)*num/den  8.4 MB

__device__ __forceinline__ void cp16(uint32_t saddr, const void* gptr) {
    asm volatile("cp.async.cg.shared.global [%0], [%1], 16;" :: "r"(saddr), "l"(gptr));
}
#define CP_COMMIT() asm volatile("cp.async.commit_group;" ::: "memory")
#define CP_WAIT1()  asm volatile("cp.async.wait_group 1;" ::: "memory")
#define CP_WAIT0()  asm volatile("cp.async.wait_group 0;" ::: "memory")

// ---------------------------------------------------------------------------
// Elementwise prep kernels
// ---------------------------------------------------------------------------
__global__ __launch_bounds__(256) void cvt_f2h_kernel(
    const float* __restrict__ in, __half* __restrict__ out)
{
    size_t i = (size_t)blockIdx.x * 256 + threadIdx.x;  // 16 elems / thread
    float4 a = reinterpret_cast<const float4*>(in)[4 * i];
    float4 b = reinterpret_cast<const float4*>(in)[4 * i + 1];
    float4 c = reinterpret_cast<const float4*>(in)[4 * i + 2];
    float4 d = reinterpret_cast<const float4*>(in)[4 * i + 3];
    __half2 h[8];
    h[0] = __floats2half2_rn(a.x, a.y); h[1] = __floats2half2_rn(a.z, a.w);
    h[2] = __floats2half2_rn(b.x, b.y); h[3] = __floats2half2_rn(b.z, b.w);
    h[4] = __floats2half2_rn(c.x, c.y); h[5] = __floats2half2_rn(c.z, c.w);
    h[6] = __floats2half2_rn(d.x, d.y); h[7] = __floats2half2_rn(d.z, d.w);
    reinterpret_cast<uint4*>(out)[2 * i]     = reinterpret_cast<uint4*>(h)[0];
    reinterpret_cast<uint4*>(out)[2 * i + 1] = reinterpret_cast<uint4*>(h)[1];
}

__global__ __launch_bounds__(256) void prep_wkv_h_kernel(
    const float* __restrict__ wk, const float* __restrict__ wv)
{
    int idx = blockIdx.x * 256 + threadIdx.x;   // k*256 + j
    reinterpret_cast<__half2*>(g_wkvh)[idx] = __floats2half2_rn(wk[idx], wv[idx]);
}

__global__ __launch_bounds__(256) void exp_bias_h_kernel(
    const float* __restrict__ bias, __half* __restrict__ out)
{
    size_t i = (size_t)blockIdx.x * 256 + threadIdx.x;  // 16 elems / thread
    float4 a = reinterpret_cast<const float4*>(bias)[4 * i];
    float4 b = reinterpret_cast<const float4*>(bias)[4 * i + 1];
    float4 c = reinterpret_cast<const float4*>(bias)[4 * i + 2];
    float4 d = reinterpret_cast<const float4*>(bias)[4 * i + 3];
    __half2 h[8];
    h[0] = __floats2half2_rn(__expf(a.x), __expf(a.y));
    h[1] = __floats2half2_rn(__expf(a.z), __expf(a.w));
    h[2] = __floats2half2_rn(__expf(b.x), __expf(b.y));
    h[3] = __floats2half2_rn(__expf(b.z), __expf(b.w));
    h[4] = __floats2half2_rn(__expf(c.x), __expf(c.y));
    h[5] = __floats2half2_rn(__expf(c.z), __expf(c.w));
    h[6] = __floats2half2_rn(__expf(d.x), __expf(d.y));
    h[7] = __floats2half2_rn(__expf(d.z), __expf(d.w));
    reinterpret_cast<uint4*>(out)[2 * i]     = reinterpret_cast<uint4*>(h)[0];
    reinterpret_cast<uint4*>(out)[2 * i + 1] = reinterpret_cast<uint4*>(h)[1];
}

// ===========================================================================
// fp16 GEMM (R11 config, frozen): BM=128 BN=128 BK=64, m16n16k16, 8 warps
// (4x2), warp tile 32x64, 3-stage cp.async pipeline.
// Row-major A, row-major B. Grid: (N/128, M/128, z)
// EPI: 0 = Oh(fp16) = sigmoid(x + v0[col])
//      1 = pairwise (K,V) -> Oh interleaved fp16 (ekv, expK)
//      2 = AFT: Oh(fp16) = aux(fp16) * num/den from adjacent (even,odd) cols
//      3 = Of = x + v0
// ===========================================================================
#define HA_STRIDE 72
#define HB_STRIDE 136
#define HSTAGE    (128 * HA_STRIDE + 64 * HB_STRIDE)   // 17920 halves
#define SMEM16    (3 * HSTAGE * 2)                     // 107520 B
#define STG_STRIDE 68
#define STG_WARP   (32 * STG_STRIDE)

template<int EPI>
__global__ __launch_bounds__(256, 2) void gemm16_kernel(
    const __half* __restrict__ A, int lda, unsigned long long sAz,
    const __half* __restrict__ Bg, int ldb, unsigned long long sBz, int Ktot,
    const float* __restrict__ v0, const float* __restrict__ v1,
    const __half* __restrict__ aux, unsigned long long sXz,
    float* __restrict__ Of, __half* __restrict__ Oh, int ldo,
    unsigned long long sOz)
{
    extern __shared__ __align__(16) float smf[];
    __half* sm = reinterpret_cast<__half*>(smf);
    const int tid = threadIdx.x, wid = tid >> 5, lane = tid & 31;
    const int n0 = blockIdx.x * 128, m0 = blockIdx.y * 128;
    const int z = blockIdx.z;
    const int wm = wid >> 1, wn = wid & 1;

    const __half* Ab = A + (size_t)z * sAz + (size_t)m0 * lda;
    const __half* Bb = Bg + (size_t)z * sBz;

    using FA = wmma::fragment<wmma::matrix_a, 16, 16, 16, __half, wmma::row_major>;
    using FB = wmma::fragment<wmma::matrix_b, 16, 16, 16, __half, wmma::row_major>;
    using FC = wmma::fragment<wmma::accumulator, 16, 16, 16, float>;

    FC acc[2][4];
#pragma unroll
    for (int mi = 0; mi < 2; mi++)
#pragma unroll
        for (int ni = 0; ni < 4; ni++)
            wmma::fill_fragment(acc[mi][ni], 0.0f);

    auto load = [&](int c) {
        __half* base = sm + (c % 3) * HSTAGE;
        const int k0 = c * 64;
#pragma unroll
        for (int i = 0; i < 4; i++) {       // A: 128x64 halves
            int idx = tid + i * 256;
            int r = idx >> 3, c8 = idx & 7;
            cp16((uint32_t)__cvta_generic_to_shared(base + r * HA_STRIDE + c8 * 8),
                 Ab + (size_t)r * lda + k0 + c8 * 8);
        }
#pragma unroll
        for (int i = 0; i < 4; i++) {       // B: 64x128 halves
            int idx = tid + i * 256;
            int r = idx >> 4, c8 = idx & 15;
            cp16((uint32_t)__cvta_generic_to_shared(
                     base + 128 * HA_STRIDE + r * HB_STRIDE + c8 * 8),
                 Bb + (size_t)(k0 + r) * ldb + n0 + c8 * 8);
        }
        CP_COMMIT();
    };

    const int nchunk = Ktot / 64;
    load(0);
    load(1);

    for (int c = 0; c < nchunk; c++) {
        if (c + 1 < nchunk) CP_WAIT1(); else CP_WAIT0();
        __syncthreads();
        if (c + 2 < nchunk) load(c + 2);

        __half* Abase = sm + (c % 3) * HSTAGE;
        __half* Bbase = Abase + 128 * HA_STRIDE;
#pragma unroll
        for (int kk = 0; kk < 4; kk++) {
            FA a[2];
#pragma unroll
            for (int mi = 0; mi < 2; mi++)
                wmma::load_matrix_sync(a[mi],
                    Abase + (wm * 32 + mi * 16) * HA_STRIDE + kk * 16, HA_STRIDE);
#pragma unroll
            for (int ni = 0; ni < 4; ni++) {
                FB b;
                wmma::load_matrix_sync(b,
                    Bbase + kk * 16 * HB_STRIDE + wn * 64 + ni * 16, HB_STRIDE);
#pragma unroll
                for (int mi = 0; mi < 2; mi++)
                    wmma::mma_sync(acc[mi][ni], a[mi], b, acc[mi][ni]);
            }
        }
    }

    // ---- Epilogue: per-warp smem staging ----
    __syncthreads();
    float* stage = smf + wid * STG_WARP;
#pragma unroll
    for (int mi = 0; mi < 2; mi++)
#pragma unroll
        for (int ni = 0; ni < 4; ni++)
            wmma::store_matrix_sync(stage + mi * 16 * STG_STRIDE + ni * 16,
                                    acc[mi][ni], STG_STRIDE, wmma::mem_row_major);
    __syncwarp();

    const int grow  = m0 + wm * 32 + lane;
    const int gcolb = n0 + wn * 64;

    if (EPI == 2) {
        // AFT epilogue: adjacent (even=num, odd=den) -> 32 fp16 h values
        const int hb = gcolb >> 1;
        const __half* sqp = aux + (size_t)z * sXz + (size_t)grow * HH + hb;
        __half2 sq2[16];
#pragma unroll
        for (int i = 0; i < 4; i++)
            reinterpret_cast<uint4*>(sq2)[i] = reinterpret_cast<const uint4*>(sqp)[i];
        float yt[32];
#pragma unroll
        for (int c4 = 0; c4 < 16; c4++) {
            float4 v = *reinterpret_cast<float4*>(stage + lane * STG_STRIDE + c4 * 4);
            yt[c4 * 2 + 0] = __fdividef(v.x, v.y);
            yt[c4 * 2 + 1] = __fdividef(v.z, v.w);
        }
        __half2 hv[16];
#pragma unroll
        for (int t = 0; t < 16; t++) {
            float2 s = __half22float2(sq2[t]);
            hv[t] = __floats2half2_rn(s.x * yt[t * 2 + 0], s.y * yt[t * 2 + 1]);
        }
        uint4* dst = reinterpret_cast<uint4*>(Oh + (size_t)z * sOz + (size_t)grow * HH + hb);
#pragma unroll
        for (int i = 0; i < 4; i++)
            dst[i] = reinterpret_cast<uint4*>(hv)[i];
    } else {
#pragma unroll
        for (int c4 = 0; c4 < 16; c4++) {
            float4 v = *reinterpret_cast<float4*>(stage + lane * STG_STRIDE + c4 * 4);
            int gc = gcolb + c4 * 4;
            if (EPI == 0) {
                float4 bv = *reinterpret_cast<const float4*>(v0 + gc);
                __half2* po = reinterpret_cast<__half2*>(
                    Oh + (size_t)z * sOz + (size_t)grow * ldo + gc);
                po[0] = __floats2half2_rn(1.0f / (1.0f + __expf(-(v.x + bv.x))),
                                          1.0f / (1.0f + __expf(-(v.y + bv.y))));
                po[1] = __floats2half2_rn(1.0f / (1.0f + __expf(-(v.z + bv.z))),
                                          1.0f / (1.0f + __expf(-(v.w + bv.w))));
            } else if (EPI == 1) {  // (v.x=K_j, v.y=V_j, v.z=K_{j+1}, v.w=V_{j+1})
                int j = gc >> 1;
                float ek0 = __expf(v.x + v0[j]);
                float kv0 = ek0 * (v.y + v1[j]);
                float ek1 = __expf(v.z + v0[j + 1]);
                float kv1 = ek1 * (v.w + v1[j + 1]);
                __half2* po = reinterpret_cast<__half2*>(
                    Oh + (size_t)z * sOz + (size_t)grow * ldo + gc);
                po[0] = __floats2half2_rn(kv0, ek0);   // cols (2j, 2j+1) = (ekv, expK)
                po[1] = __floats2half2_rn(kv1, ek1);
            } else {  // EPI == 3: linear + bias
                float4 bv = *reinterpret_cast<const float4*>(v0 + gc);
                float4 ov;
                ov.x = v.x + bv.x; ov.y = v.y + bv.y;
                ov.z = v.z + bv.z; ov.w = v.w + bv.w;
                *reinterpret_cast<float4*>(Of + (size_t)z * sOz + (size_t)grow * ldo + gc) = ov;
            }
        }
    }
}

// ---------------------------------------------------------------------------
// Launch: R15 topology with asymmetric aft split 4+3+1 and outproj 4+3+1 so
// only the final 1-batch outproj (~3 us) remains exposed.
// Inputs (metadata order):
//  0:x_q 1:x_kv 2:bias 3:wq_w 4:wq_b 5:wk_w 6:wk_b 7:wv_w 8:wv_b 9:f2_w 10:f2_b
// ---------------------------------------------------------------------------
extern "C" void kernel_launch(void* const* d_in, const int* in_sizes, int n_in,
                              void* d_out, int out_size) {
    (void)in_sizes; (void)n_in; (void)out_size;
    const float* x_q  = (const float*)d_in[0];
    const float* x_kv = (const float*)d_in[1];
    const float* bias = (const float*)d_in[2];
    const float* wq_w = (const float*)d_in[3];
    const float* wq_b = (const float*)d_in[4];
    const float* wk_w = (const float*)d_in[5];
    const float* wk_b = (const float*)d_in[6];
    const float* wv_w = (const float*)d_in[7];
    const float* wv_b = (const float*)d_in[8];
    const float* f2_w = (const float*)d_in[9];
    const float* f2_b = (const float*)d_in[10];
    float* out = (float*)d_out;

    __half *p_expwh, *p_xqh, *p_xkvh, *p_wqh, *p_wkvh, *p_f2h, *p_kvi, *p_sigQh, *p_Yth;
    cudaGetSymbolAddress((void**)&p_expwh, g_expwh);
    cudaGetSymbolAddress((void**)&p_xqh,   g_xqh);
    cudaGetSymbolAddress((void**)&p_xkvh,  g_xkvh);
    cudaGetSymbolAddress((void**)&p_wqh,   g_wqh);
    cudaGetSymbolAddress((void**)&p_wkvh,  g_wkvh);
    cudaGetSymbolAddress((void**)&p_f2h,   g_f2h);
    cudaGetSymbolAddress((void**)&p_kvi,   g_kvi);
    cudaGetSymbolAddress((void**)&p_sigQh, g_sigQh);
    cudaGetSymbolAddress((void**)&p_Yth,   g_Yth);

    // One-time host-side objects (no device memory involved)
    static cudaStream_t s1 = nullptr, s2 = nullptr, s3 = nullptr;
    static cudaEvent_t evRoot = nullptr, evKviH = nullptr, evKvi = nullptr;
    static cudaEvent_t evExpH = nullptr, evS2 = nullptr;
    static cudaEvent_t evAftA = nullptr, evAftB = nullptr, evOut = nullptr;
    static cudaEvent_t evCvt[NGRP] = {};
    static bool attrs_set = false;
    if (!s1) {
        cudaStreamCreateWithFlags(&s1, cudaStreamNonBlocking);
        cudaStreamCreateWithFlags(&s2, cudaStreamNonBlocking);
        cudaStreamCreateWithFlags(&s3, cudaStreamNonBlocking);
        cudaEventCreateWithFlags(&evRoot, cudaEventDisableTiming);
        cudaEventCreateWithFlags(&evKviH, cudaEventDisableTiming);
        cudaEventCreateWithFlags(&evKvi, cudaEventDisableTiming);
        cudaEventCreateWithFlags(&evExpH, cudaEventDisableTiming);
        cudaEventCreateWithFlags(&evS2, cudaEventDisableTiming);
        cudaEventCreateWithFlags(&evAftA, cudaEventDisableTiming);
        cudaEventCreateWithFlags(&evAftB, cudaEventDisableTiming);
        cudaEventCreateWithFlags(&evOut, cudaEventDisableTiming);
        for (int g = 0; g < NGRP; g++)
            cudaEventCreateWithFlags(&evCvt[g], cudaEventDisableTiming);
    }
    if (!attrs_set) {
        cudaFuncSetAttribute((const void*)gemm16_kernel<0>,
                             cudaFuncAttributeMaxDynamicSharedMemorySize, SMEM16);
        cudaFuncSetAttribute((const void*)gemm16_kernel<1>,
                             cudaFuncAttributeMaxDynamicSharedMemorySize, SMEM16);
        cudaFuncSetAttribute((const void*)gemm16_kernel<2>,
                             cudaFuncAttributeMaxDynamicSharedMemorySize, SMEM16);
        cudaFuncSetAttribute((const void*)gemm16_kernel<3>,
                             cudaFuncAttributeMaxDynamicSharedMemorySize, SMEM16);
        attrs_set = true;
    }

    const unsigned long long sAz = (unsigned long long)NQ * NKV;
    const unsigned long long sBz = (unsigned long long)NKV * NI;
    const unsigned long long sXz = (unsigned long long)NQ * HH;

    // ---- fork ----
    cudaEventRecord(evRoot, 0);
    cudaStreamWaitEvent(s1, evRoot, 0);
    cudaStreamWaitEvent(s2, evRoot, 0);
    cudaStreamWaitEvent(s3, evRoot, 0);

    // Chain KV-cvt (s1): wkv prep, then per-group x_kv conversion
    prep_wkv_h_kernel<<<(DKV * HH) / 256, 256, 0, s1>>>(wk_w, wv_w);
    for (int g = 0; g < NGRP; g++) {
        const size_t off = (size_t)g * BPG * NKV * DKV;
        cvt_f2h_kernel<<<(BPG * NKV * DKV) / 16 / 256, 256, 0, s1>>>(
            x_kv + off, p_xkvh + off);
        cudaEventRecord(evCvt[g], s1);
    }

    // Chain KV-gemm (s3): per-group kvi GEMM, overlapped with next cvt
    for (int g = 0; g < NGRP; g++) {
        cudaStreamWaitEvent(s3, evCvt[g], 0);
        dim3 grid(NI / 128, (BPG * NKV) / 128, 1);
        gemm16_kernel<1><<<grid, 256, SMEM16, s3>>>(
            p_xkvh + (size_t)g * BPG * NKV * DKV, DKV, 0ull,
            p_wkvh, NI, 0ull, DKV,
            wk_b, wv_b, nullptr, 0ull,
            nullptr, p_kvi + (size_t)g * BPG * NKV * NI, NI, 0ull);
        if (g == 1) cudaEventRecord(evKviH, s3);   // batches 0-3 done
    }
    cudaEventRecord(evKvi, s3);

    // Chain bias + f2 (s2): f2_w cvt, then exp(bias) in two 4-batch halves
    cvt_f2h_kernel<<<(HH * HH) / 16 / 256, 256, 0, s2>>>(f2_w, p_f2h);
    {
        const size_t hn = (size_t)HALFB * NQ * NKV;
        exp_bias_h_kernel<<<(unsigned)(hn / 16 / 256), 256, 0, s2>>>(bias, p_expwh);
        cudaEventRecord(evExpH, s2);
        exp_bias_h_kernel<<<(unsigned)(hn / 16 / 256), 256, 0, s2>>>(bias + hn, p_expwh + hn);
    }
    cudaEventRecord(evS2, s2);

    // Chain Q (capture stream 0): cvt wq, cvt x_q -> sigQ (fp16 out)
    cvt_f2h_kernel<<<(DQ * HH) / 16 / 256, 256>>>(wq_w, p_wqh);
    cvt_f2h_kernel<<<(BATCH * NQ * DQ) / 16 / 256, 256>>>(x_q, p_xqh);
    {
        dim3 grid(HH / 128, (BATCH * NQ) / 128, 1);
        gemm16_kernel<0><<<grid, 256, SMEM16>>>(
            p_xqh, DQ, 0ull, p_wqh, HH, 0ull, DQ,
            wq_b, nullptr, nullptr, 0ull, nullptr, p_sigQh, HH, 0ull);
    }

    // ---- AFT part A (batches 0-3): gated on kvi half + exp half ----
    cudaStreamWaitEvent(0, evKviH, 0);
    cudaStreamWaitEvent(0, evExpH, 0);
    {
        dim3 grid(NI / 128, NQ / 128, 4);
        gemm16_kernel<2><<<grid, 256, SMEM16>>>(
            p_expwh, NKV, sAz, p_kvi, NI, sBz, NKV,
            nullptr, nullptr, p_sigQh, sXz,
            nullptr, p_Yth, NI, sXz);
    }
    cudaEventRecord(evAftA, 0);

    // ---- AFT part B (batches 4-6): gated on full kvi + full exp ----
    cudaStreamWaitEvent(0, evKvi, 0);
    cudaStreamWaitEvent(0, evS2, 0);
    {
        dim3 grid(NI / 128, NQ / 128, 3);
        gemm16_kernel<2><<<grid, 256, SMEM16>>>(
            p_expwh + 4 * sAz, NKV, sAz, p_kvi + 4 * sBz, NI, sBz, NKV,
            nullptr, nullptr, p_sigQh + 4 * sXz, sXz,
            nullptr, p_Yth + 4 * sXz, NI, sXz);
    }
    cudaEventRecord(evAftB, 0);

    // ---- AFT part C (batch 7) on capture stream ----
    {
        dim3 grid(NI / 128, NQ / 128, 1);
        gemm16_kernel<2><<<grid, 256, SMEM16>>>(
            p_expwh + 7 * sAz, NKV, sAz, p_kvi + 7 * sBz, NI, sBz, NKV,
            nullptr, nullptr, p_sigQh + 7 * sXz, sXz,
            nullptr, p_Yth + 7 * sXz, NI, sXz);
    }

    // ---- outproj P0 (batches 0-3) on s2: overlaps aft B/C ----
    cudaStreamWaitEvent(s2, evAftA, 0);
    {
        dim3 grid(HH / 128, (4 * NQ) / 128, 1);
        gemm16_kernel<3><<<grid, 256, SMEM16, s2>>>(
            p_Yth, HH, 0ull, p_f2h, HH, 0ull, HH,
            f2_b, nullptr, nullptr, 0ull, out, nullptr, HH, 0ull);
    }
    // ---- outproj P1 (batches 4-6) on s2: overlaps aft C ----
    cudaStreamWaitEvent(s2, evAftB, 0);
    {
        dim3 grid(HH / 128, (3 * NQ) / 128, 1);
        gemm16_kernel<3><<<grid, 256, SMEM16, s2>>>(
            p_Yth + 4 * sXz, HH, 0ull, p_f2h, HH, 0ull, HH,
            f2_b, nullptr, nullptr, 0ull, out + 4 * sXz, nullptr, HH, 0ull);
    }
    cudaEventRecord(evOut, s2);

    // ---- outproj P2 (batch 7) on capture stream (after aft C) ----
    {
        dim3 grid(HH / 128, NQ / 128, 1);
        gemm16_kernel<3><<<grid, 256, SMEM16>>>(
            p_Yth + 7 * sXz, HH, 0ull, p_f2h, HH, 0ull, HH,
            f2_b, nullptr, nullptr, 0ull, out + 7 * sXz, nullptr, HH, 0ull);
    }

    // ---- join ----
    cudaStreamWaitEvent(0, evOut, 0);
}

// round 17
// speedup vs baseline: 1.1387x; 1.1387x over previous
#include <cuda_runtime.h>
#include <cuda_fp16.h>
#include <mma.h>
#include <cstdint>

using namespace nvcuda;

// Problem dims (fixed)
#define BATCH 8
#define NQ    2048
#define NKV   2048
#define DQ    1024
#define DKV   1024
#define HH    256
#define NI    512            // interleaved (num,den) width
#define BPG   2              // batches per KV pipeline group
#define NGRP  (BATCH / BPG)  // 4
#define HALFB (BATCH / 2)    // 4 batches per aft/outproj half

// Scratch (device globals — no allocation allowed)
__device__ __half g_expwh[(size_t)BATCH * NQ * NKV]; // fp16 exp(bias)       67 MB
__device__ __half g_xqh  [BATCH * NQ * DQ];          // fp16 x_q             33.5 MB
__device__ __half g_xkvh [BATCH * NKV * DKV];        // fp16 x_kv            33.5 MB
__device__ __half g_wqh  [DQ * HH];                  // fp16 wq              0.5 MB
__device__ __half g_wkvh [DKV * NI];                 // fp16 interleaved wk|wv 1 MB
__device__ __half g_f2h  [HH * HH];                  // fp16 f2_w            0.13 MB
__device__ __half g_kvi  [BATCH * NKV * NI];         // interleaved ekv/expK 16.8 MB
__device__ __half g_sigQh[BATCH * NQ * HH];          // fp16 sigmoid(Q)      8.4 MB
__device__ __half g_Yth  [BATCH * NQ * HH];          // fp16 sig(Q)*num/den  8.4 MB

__device__ __forceinline__ void cp16(uint32_t saddr, const void* gptr) {
    asm volatile("cp.async.cg.shared.global [%0], [%1], 16;" :: "r"(saddr), "l"(gptr));
}
#define CP_COMMIT() asm volatile("cp.async.commit_group;" ::: "memory")
#define CP_WAIT1()  asm volatile("cp.async.wait_group 1;" ::: "memory")
#define CP_WAIT0()  asm volatile("cp.async.wait_group 0;" ::: "memory")

// ---------------------------------------------------------------------------
// Elementwise prep kernels
// ---------------------------------------------------------------------------
__global__ __launch_bounds__(256) void cvt_f2h_kernel(
    const float* __restrict__ in, __half* __restrict__ out)
{
    size_t i = (size_t)blockIdx.x * 256 + threadIdx.x;  // 16 elems / thread
    float4 a = reinterpret_cast<const float4*>(in)[4 * i];
    float4 b = reinterpret_cast<const float4*>(in)[4 * i + 1];
    float4 c = reinterpret_cast<const float4*>(in)[4 * i + 2];
    float4 d = reinterpret_cast<const float4*>(in)[4 * i + 3];
    __half2 h[8];
    h[0] = __floats2half2_rn(a.x, a.y); h[1] = __floats2half2_rn(a.z, a.w);
    h[2] = __floats2half2_rn(b.x, b.y); h[3] = __floats2half2_rn(b.z, b.w);
    h[4] = __floats2half2_rn(c.x, c.y); h[5] = __floats2half2_rn(c.z, c.w);
    h[6] = __floats2half2_rn(d.x, d.y); h[7] = __floats2half2_rn(d.z, d.w);
    reinterpret_cast<uint4*>(out)[2 * i]     = reinterpret_cast<uint4*>(h)[0];
    reinterpret_cast<uint4*>(out)[2 * i + 1] = reinterpret_cast<uint4*>(h)[1];
}

__global__ __launch_bounds__(256) void prep_wkv_h_kernel(
    const float* __restrict__ wk, const float* __restrict__ wv)
{
    int idx = blockIdx.x * 256 + threadIdx.x;   // k*256 + j
    reinterpret_cast<__half2*>(g_wkvh)[idx] = __floats2half2_rn(wk[idx], wv[idx]);
}

__global__ __launch_bounds__(256) void exp_bias_h_kernel(
    const float* __restrict__ bias, __half* __restrict__ out)
{
    size_t i = (size_t)blockIdx.x * 256 + threadIdx.x;  // 16 elems / thread
    float4 a = reinterpret_cast<const float4*>(bias)[4 * i];
    float4 b = reinterpret_cast<const float4*>(bias)[4 * i + 1];
    float4 c = reinterpret_cast<const float4*>(bias)[4 * i + 2];
    float4 d = reinterpret_cast<const float4*>(bias)[4 * i + 3];
    __half2 h[8];
    h[0] = __floats2half2_rn(__expf(a.x), __expf(a.y));
    h[1] = __floats2half2_rn(__expf(a.z), __expf(a.w));
    h[2] = __floats2half2_rn(__expf(b.x), __expf(b.y));
    h[3] = __floats2half2_rn(__expf(b.z), __expf(b.w));
    h[4] = __floats2half2_rn(__expf(c.x), __expf(c.y));
    h[5] = __floats2half2_rn(__expf(c.z), __expf(c.w));
    h[6] = __floats2half2_rn(__expf(d.x), __expf(d.y));
    h[7] = __floats2half2_rn(__expf(d.z), __expf(d.w));
    reinterpret_cast<uint4*>(out)[2 * i]     = reinterpret_cast<uint4*>(h)[0];
    reinterpret_cast<uint4*>(out)[2 * i + 1] = reinterpret_cast<uint4*>(h)[1];
}

// ===========================================================================
// fp16 GEMM (R11 config, frozen): BM=128 BN=128 BK=64, m16n16k16, 8 warps
// (4x2), warp tile 32x64, 3-stage cp.async pipeline.
// Row-major A, row-major B. Grid: (N/128, M/128, z)
// EPI: 0 = Oh(fp16) = sigmoid(x + v0[col])
//      1 = pairwise (K,V) -> Oh interleaved fp16 (ekv, expK)
//      2 = AFT: Oh(fp16) = aux(fp16) * num/den from adjacent (even,odd) cols
//      3 = Of = x + v0
// ===========================================================================
#define HA_STRIDE 72
#define HB_STRIDE 136
#define HSTAGE    (128 * HA_STRIDE + 64 * HB_STRIDE)   // 17920 halves
#define SMEM16    (3 * HSTAGE * 2)                     // 107520 B
#define STG_STRIDE 68
#define STG_WARP   (32 * STG_STRIDE)

template<int EPI>
__global__ __launch_bounds__(256, 2) void gemm16_kernel(
    const __half* __restrict__ A, int lda, unsigned long long sAz,
    const __half* __restrict__ Bg, int ldb, unsigned long long sBz, int Ktot,
    const float* __restrict__ v0, const float* __restrict__ v1,
    const __half* __restrict__ aux, unsigned long long sXz,
    float* __restrict__ Of, __half* __restrict__ Oh, int ldo,
    unsigned long long sOz)
{
    extern __shared__ __align__(16) float smf[];
    __half* sm = reinterpret_cast<__half*>(smf);
    const int tid = threadIdx.x, wid = tid >> 5, lane = tid & 31;
    const int n0 = blockIdx.x * 128, m0 = blockIdx.y * 128;
    const int z = blockIdx.z;
    const int wm = wid >> 1, wn = wid & 1;

    const __half* Ab = A + (size_t)z * sAz + (size_t)m0 * lda;
    const __half* Bb = Bg + (size_t)z * sBz;

    using FA = wmma::fragment<wmma::matrix_a, 16, 16, 16, __half, wmma::row_major>;
    using FB = wmma::fragment<wmma::matrix_b, 16, 16, 16, __half, wmma::row_major>;
    using FC = wmma::fragment<wmma::accumulator, 16, 16, 16, float>;

    FC acc[2][4];
#pragma unroll
    for (int mi = 0; mi < 2; mi++)
#pragma unroll
        for (int ni = 0; ni < 4; ni++)
            wmma::fill_fragment(acc[mi][ni], 0.0f);

    auto load = [&](int c) {
        __half* base = sm + (c % 3) * HSTAGE;
        const int k0 = c * 64;
#pragma unroll
        for (int i = 0; i < 4; i++) {       // A: 128x64 halves
            int idx = tid + i * 256;
            int r = idx >> 3, c8 = idx & 7;
            cp16((uint32_t)__cvta_generic_to_shared(base + r * HA_STRIDE + c8 * 8),
                 Ab + (size_t)r * lda + k0 + c8 * 8);
        }
#pragma unroll
        for (int i = 0; i < 4; i++) {       // B: 64x128 halves
            int idx = tid + i * 256;
            int r = idx >> 4, c8 = idx & 15;
            cp16((uint32_t)__cvta_generic_to_shared(
                     base + 128 * HA_STRIDE + r * HB_STRIDE + c8 * 8),
                 Bb + (size_t)(k0 + r) * ldb + n0 + c8 * 8);
        }
        CP_COMMIT();
    };

    const int nchunk = Ktot / 64;
    load(0);
    load(1);

    for (int c = 0; c < nchunk; c++) {
        if (c + 1 < nchunk) CP_WAIT1(); else CP_WAIT0();
        __syncthreads();
        if (c + 2 < nchunk) load(c + 2);

        __half* Abase = sm + (c % 3) * HSTAGE;
        __half* Bbase = Abase + 128 * HA_STRIDE;
#pragma unroll
        for (int kk = 0; kk < 4; kk++) {
            FA a[2];
#pragma unroll
            for (int mi = 0; mi < 2; mi++)
                wmma::load_matrix_sync(a[mi],
                    Abase + (wm * 32 + mi * 16) * HA_STRIDE + kk * 16, HA_STRIDE);
#pragma unroll
            for (int ni = 0; ni < 4; ni++) {
                FB b;
                wmma::load_matrix_sync(b,
                    Bbase + kk * 16 * HB_STRIDE + wn * 64 + ni * 16, HB_STRIDE);
#pragma unroll
                for (int mi = 0; mi < 2; mi++)
                    wmma::mma_sync(acc[mi][ni], a[mi], b, acc[mi][ni]);
            }
        }
    }

    // ---- Epilogue: per-warp smem staging ----
    __syncthreads();
    float* stage = smf + wid * STG_WARP;
#pragma unroll
    for (int mi = 0; mi < 2; mi++)
#pragma unroll
        for (int ni = 0; ni < 4; ni++)
            wmma::store_matrix_sync(stage + mi * 16 * STG_STRIDE + ni * 16,
                                    acc[mi][ni], STG_STRIDE, wmma::mem_row_major);
    __syncwarp();

    const int grow  = m0 + wm * 32 + lane;
    const int gcolb = n0 + wn * 64;

    if (EPI == 2) {
        // AFT epilogue: adjacent (even=num, odd=den) -> 32 fp16 h values
        const int hb = gcolb >> 1;
        const __half* sqp = aux + (size_t)z * sXz + (size_t)grow * HH + hb;
        __half2 sq2[16];
#pragma unroll
        for (int i = 0; i < 4; i++)
            reinterpret_cast<uint4*>(sq2)[i] = reinterpret_cast<const uint4*>(sqp)[i];
        float yt[32];
#pragma unroll
        for (int c4 = 0; c4 < 16; c4++) {
            float4 v = *reinterpret_cast<float4*>(stage + lane * STG_STRIDE + c4 * 4);
            yt[c4 * 2 + 0] = __fdividef(v.x, v.y);
            yt[c4 * 2 + 1] = __fdividef(v.z, v.w);
        }
        __half2 hv[16];
#pragma unroll
        for (int t = 0; t < 16; t++) {
            float2 s = __half22float2(sq2[t]);
            hv[t] = __floats2half2_rn(s.x * yt[t * 2 + 0], s.y * yt[t * 2 + 1]);
        }
        uint4* dst = reinterpret_cast<uint4*>(Oh + (size_t)z * sOz + (size_t)grow * HH + hb);
#pragma unroll
        for (int i = 0; i < 4; i++)
            dst[i] = reinterpret_cast<uint4*>(hv)[i];
    } else {
#pragma unroll
        for (int c4 = 0; c4 < 16; c4++) {
            float4 v = *reinterpret_cast<float4*>(stage + lane * STG_STRIDE + c4 * 4);
            int gc = gcolb + c4 * 4;
            if (EPI == 0) {
                float4 bv = *reinterpret_cast<const float4*>(v0 + gc);
                __half2* po = reinterpret_cast<__half2*>(
                    Oh + (size_t)z * sOz + (size_t)grow * ldo + gc);
                po[0] = __floats2half2_rn(1.0f / (1.0f + __expf(-(v.x + bv.x))),
                                          1.0f / (1.0f + __expf(-(v.y + bv.y))));
                po[1] = __floats2half2_rn(1.0f / (1.0f + __expf(-(v.z + bv.z))),
                                          1.0f / (1.0f + __expf(-(v.w + bv.w))));
            } else if (EPI == 1) {  // (v.x=K_j, v.y=V_j, v.z=K_{j+1}, v.w=V_{j+1})
                int j = gc >> 1;
                float ek0 = __expf(v.x + v0[j]);
                float kv0 = ek0 * (v.y + v1[j]);
                float ek1 = __expf(v.z + v0[j + 1]);
                float kv1 = ek1 * (v.w + v1[j + 1]);
                __half2* po = reinterpret_cast<__half2*>(
                    Oh + (size_t)z * sOz + (size_t)grow * ldo + gc);
                po[0] = __floats2half2_rn(kv0, ek0);   // cols (2j, 2j+1) = (ekv, expK)
                po[1] = __floats2half2_rn(kv1, ek1);
            } else {  // EPI == 3: linear + bias
                float4 bv = *reinterpret_cast<const float4*>(v0 + gc);
                float4 ov;
                ov.x = v.x + bv.x; ov.y = v.y + bv.y;
                ov.z = v.z + bv.z; ov.w = v.w + bv.w;
                *reinterpret_cast<float4*>(Of + (size_t)z * sOz + (size_t)grow * ldo + gc) = ov;
            }
        }
    }
}

// ---------------------------------------------------------------------------
// Launch: R14 topology + per-half exp(bias) gating + fp16 sigQ.
// Inputs (metadata order):
//  0:x_q 1:x_kv 2:bias 3:wq_w 4:wq_b 5:wk_w 6:wk_b 7:wv_w 8:wv_b 9:f2_w 10:f2_b
// ---------------------------------------------------------------------------
extern "C" void kernel_launch(void* const* d_in, const int* in_sizes, int n_in,
                              void* d_out, int out_size) {
    (void)in_sizes; (void)n_in; (void)out_size;
    const float* x_q  = (const float*)d_in[0];
    const float* x_kv = (const float*)d_in[1];
    const float* bias = (const float*)d_in[2];
    const float* wq_w = (const float*)d_in[3];
    const float* wq_b = (const float*)d_in[4];
    const float* wk_w = (const float*)d_in[5];
    const float* wk_b = (const float*)d_in[6];
    const float* wv_w = (const float*)d_in[7];
    const float* wv_b = (const float*)d_in[8];
    const float* f2_w = (const float*)d_in[9];
    const float* f2_b = (const float*)d_in[10];
    float* out = (float*)d_out;

    __half *p_expwh, *p_xqh, *p_xkvh, *p_wqh, *p_wkvh, *p_f2h, *p_kvi, *p_sigQh, *p_Yth;
    cudaGetSymbolAddress((void**)&p_expwh, g_expwh);
    cudaGetSymbolAddress((void**)&p_xqh,   g_xqh);
    cudaGetSymbolAddress((void**)&p_xkvh,  g_xkvh);
    cudaGetSymbolAddress((void**)&p_wqh,   g_wqh);
    cudaGetSymbolAddress((void**)&p_wkvh,  g_wkvh);
    cudaGetSymbolAddress((void**)&p_f2h,   g_f2h);
    cudaGetSymbolAddress((void**)&p_kvi,   g_kvi);
    cudaGetSymbolAddress((void**)&p_sigQh, g_sigQh);
    cudaGetSymbolAddress((void**)&p_Yth,   g_Yth);

    // One-time host-side objects (no device memory involved)
    static cudaStream_t s1 = nullptr, s2 = nullptr, s3 = nullptr;
    static cudaEvent_t evRoot = nullptr, evKviH = nullptr, evKvi = nullptr;
    static cudaEvent_t evExpH = nullptr, evS2 = nullptr, evAftH = nullptr, evOutH = nullptr;
    static cudaEvent_t evCvt[NGRP] = {};
    static bool attrs_set = false;
    if (!s1) {
        cudaStreamCreateWithFlags(&s1, cudaStreamNonBlocking);
        cudaStreamCreateWithFlags(&s2, cudaStreamNonBlocking);
        cudaStreamCreateWithFlags(&s3, cudaStreamNonBlocking);
        cudaEventCreateWithFlags(&evRoot, cudaEventDisableTiming);
        cudaEventCreateWithFlags(&evKviH, cudaEventDisableTiming);
        cudaEventCreateWithFlags(&evKvi, cudaEventDisableTiming);
        cudaEventCreateWithFlags(&evExpH, cudaEventDisableTiming);
        cudaEventCreateWithFlags(&evS2, cudaEventDisableTiming);
        cudaEventCreateWithFlags(&evAftH, cudaEventDisableTiming);
        cudaEventCreateWithFlags(&evOutH, cudaEventDisableTiming);
        for (int g = 0; g < NGRP; g++)
            cudaEventCreateWithFlags(&evCvt[g], cudaEventDisableTiming);
    }
    if (!attrs_set) {
        cudaFuncSetAttribute((const void*)gemm16_kernel<0>,
                             cudaFuncAttributeMaxDynamicSharedMemorySize, SMEM16);
        cudaFuncSetAttribute((const void*)gemm16_kernel<1>,
                             cudaFuncAttributeMaxDynamicSharedMemorySize, SMEM16);
        cudaFuncSetAttribute((const void*)gemm16_kernel<2>,
                             cudaFuncAttributeMaxDynamicSharedMemorySize, SMEM16);
        cudaFuncSetAttribute((const void*)gemm16_kernel<3>,
                             cudaFuncAttributeMaxDynamicSharedMemorySize, SMEM16);
        attrs_set = true;
    }

    // ---- fork ----
    cudaEventRecord(evRoot, 0);
    cudaStreamWaitEvent(s1, evRoot, 0);
    cudaStreamWaitEvent(s2, evRoot, 0);
    cudaStreamWaitEvent(s3, evRoot, 0);

    // Chain KV-cvt (s1): wkv prep, then per-group x_kv conversion
    prep_wkv_h_kernel<<<(DKV * HH) / 256, 256, 0, s1>>>(wk_w, wv_w);
    for (int g = 0; g < NGRP; g++) {
        const size_t off = (size_t)g * BPG * NKV * DKV;
        cvt_f2h_kernel<<<(BPG * NKV * DKV) / 16 / 256, 256, 0, s1>>>(
            x_kv + off, p_xkvh + off);
        cudaEventRecord(evCvt[g], s1);
    }

    // Chain KV-gemm (s3): per-group kvi GEMM, overlapped with next cvt
    for (int g = 0; g < NGRP; g++) {
        cudaStreamWaitEvent(s3, evCvt[g], 0);
        dim3 grid(NI / 128, (BPG * NKV) / 128, 1);
        gemm16_kernel<1><<<grid, 256, SMEM16, s3>>>(
            p_xkvh + (size_t)g * BPG * NKV * DKV, DKV, 0ull,
            p_wkvh, NI, 0ull, DKV,
            wk_b, wv_b, nullptr, 0ull,
            nullptr, p_kvi + (size_t)g * BPG * NKV * NI, NI, 0ull);
        if (g == 1) cudaEventRecord(evKviH, s3);   // first 4 batches done
    }
    cudaEventRecord(evKvi, s3);

    // Chain bias + f2 (s2): f2_w cvt, then exp(bias) in two 4-batch halves
    cvt_f2h_kernel<<<(HH * HH) / 16 / 256, 256, 0, s2>>>(f2_w, p_f2h);
    {
        const size_t hn = (size_t)HALFB * NQ * NKV;
        exp_bias_h_kernel<<<(unsigned)(hn / 16 / 256), 256, 0, s2>>>(bias, p_expwh);
        cudaEventRecord(evExpH, s2);
        exp_bias_h_kernel<<<(unsigned)(hn / 16 / 256), 256, 0, s2>>>(bias + hn, p_expwh + hn);
    }
    cudaEventRecord(evS2, s2);

    // Chain Q (capture stream 0): cvt wq, cvt x_q -> sigQ (fp16 out)
    cvt_f2h_kernel<<<(DQ * HH) / 16 / 256, 256>>>(wq_w, p_wqh);
    cvt_f2h_kernel<<<(BATCH * NQ * DQ) / 16 / 256, 256>>>(x_q, p_xqh);
    {
        dim3 grid(HH / 128, (BATCH * NQ) / 128, 1);
        gemm16_kernel<0><<<grid, 256, SMEM16>>>(
            p_xqh, DQ, 0ull, p_wqh, HH, 0ull, DQ,
            wq_b, nullptr, nullptr, 0ull, nullptr, p_sigQh, HH, 0ull);
    }

    // ---- AFT half 0 (batches 0-3): gated on kvi half + exp half ----
    cudaStreamWaitEvent(0, evKviH, 0);
    cudaStreamWaitEvent(0, evExpH, 0);
    {
        dim3 grid(NI / 128, NQ / 128, HALFB);
        gemm16_kernel<2><<<grid, 256, SMEM16>>>(
            p_expwh, NKV, (unsigned long long)NQ * NKV,
            p_kvi, NI, (unsigned long long)NKV * NI, NKV,
            nullptr, nullptr, p_sigQh, (unsigned long long)NQ * HH,
            nullptr, p_Yth, NI, (unsigned long long)NQ * HH);
    }
    cudaEventRecord(evAftH, 0);

    // ---- AFT half 1 (batches 4-7): gated on full kvi + full exp ----
    cudaStreamWaitEvent(0, evKvi, 0);
    cudaStreamWaitEvent(0, evS2, 0);
    {
        const size_t hb = (size_t)HALFB;
        dim3 grid(NI / 128, NQ / 128, HALFB);
        gemm16_kernel<2><<<grid, 256, SMEM16>>>(
            p_expwh + hb * NQ * NKV, NKV, (unsigned long long)NQ * NKV,
            p_kvi + hb * NKV * NI, NI, (unsigned long long)NKV * NI, NKV,
            nullptr, nullptr,
            p_sigQh + hb * NQ * HH, (unsigned long long)NQ * HH,
            nullptr, p_Yth + hb * NQ * HH, NI, (unsigned long long)NQ * HH);
    }

    // ---- outproj half 0 on s2 (overlaps aft half 1) ----
    cudaStreamWaitEvent(s2, evAftH, 0);
    {
        dim3 grid(HH / 128, (HALFB * NQ) / 128, 1);
        gemm16_kernel<3><<<grid, 256, SMEM16, s2>>>(
            p_Yth, HH, 0ull, p_f2h, HH, 0ull, HH,
            f2_b, nullptr, nullptr, 0ull, out, nullptr, HH, 0ull);
    }
    cudaEventRecord(evOutH, s2);

    // ---- outproj half 1 on capture stream (after aft half 1) ----
    {
        const size_t hb = (size_t)HALFB;
        dim3 grid(HH / 128, (HALFB * NQ) / 128, 1);
        gemm16_kernel<3><<<grid, 256, SMEM16>>>(
            p_Yth + hb * NQ * HH, HH, 0ull, p_f2h, HH, 0ull, HH,
            f2_b, nullptr, nullptr, 0ull, out + hb * NQ * HH, nullptr, HH, 0ull);
    }

    // ---- join ----
    cudaStreamWaitEvent(0, evOutH, 0);
}